// round 1
// baseline (speedup 1.0000x reference)
#include <cuda_runtime.h>

#define BATCH 8
#define NPTS  4096
#define MCENT 1024
#define KG    64
#define CIN   64
#define HC    128   // half of C_out

// ---------------- scratch (device globals; no allocation) ----------------
__device__ int    g_idx[BATCH * MCENT];
__device__ int    g_sel[BATCH * MCENT * KG];
__device__ float4 g_P1v[BATCH * NPTS * (CIN / 4)];   // W1·p per point, 64 floats/pt
__device__ float4 g_Fov[BATCH * NPTS * (HC / 4)];    // feature-MLP output, 128 floats/pt

// exact (no-FMA) squared distance, association ((dx^2+dy^2)+dz^2) to match XLA
__device__ __forceinline__ float sq3(float dx, float dy, float dz) {
    return __fadd_rn(__fadd_rn(__fmul_rn(dx, dx), __fmul_rn(dy, dy)), __fmul_rn(dz, dz));
}

// ======================= K_fps: farthest point sampling =======================
__global__ __launch_bounds__(1024) void fps_kernel(const float* __restrict__ points) {
    extern __shared__ float sm[];
    float* sx = sm; float* sy = sm + NPTS; float* sz = sm + 2 * NPTS;
    __shared__ float rv[32]; __shared__ int ri[32]; __shared__ int s_last;
    const int b = blockIdx.x, tid = threadIdx.x;
    const float* pb = points + b * 3 * NPTS;
    for (int i = tid; i < NPTS; i += 1024) { sx[i] = pb[i]; sy[i] = pb[NPTS + i]; sz[i] = pb[2 * NPTS + i]; }
    __syncthreads();
    const int i0 = tid * 4;
    const float x0 = sx[i0 + 0], y0 = sy[i0 + 0], z0 = sz[i0 + 0];
    const float x1 = sx[i0 + 1], y1 = sy[i0 + 1], z1 = sz[i0 + 1];
    const float x2 = sx[i0 + 2], y2 = sy[i0 + 2], z2 = sz[i0 + 2];
    const float x3 = sx[i0 + 3], y3 = sy[i0 + 3], z3 = sz[i0 + 3];
    float m0 = 1e30f, m1 = 1e30f, m2 = 1e30f, m3 = 1e30f;
    int last = 0;
    const int lane = tid & 31, w = tid >> 5;
    for (int s = 0; s < MCENT; s++) {
        if (tid == 0) g_idx[b * MCENT + s] = last;
        const float lx = sx[last], ly = sy[last], lz = sz[last];
        m0 = fminf(m0, sq3(x0 - lx, y0 - ly, z0 - lz));
        m1 = fminf(m1, sq3(x1 - lx, y1 - ly, z1 - lz));
        m2 = fminf(m2, sq3(x2 - lx, y2 - ly, z2 - lz));
        m3 = fminf(m3, sq3(x3 - lx, y3 - ly, z3 - lz));
        float bv = m0; int bi = i0;                 // strictly-greater keeps first max
        if (m1 > bv) { bv = m1; bi = i0 + 1; }
        if (m2 > bv) { bv = m2; bi = i0 + 2; }
        if (m3 > bv) { bv = m3; bi = i0 + 3; }
        #pragma unroll
        for (int off = 16; off; off >>= 1) {
            float ov = __shfl_down_sync(0xffffffffu, bv, off);
            int   oi = __shfl_down_sync(0xffffffffu, bi, off);
            if (ov > bv || (ov == bv && oi < bi)) { bv = ov; bi = oi; }
        }
        if (lane == 0) { rv[w] = bv; ri[w] = bi; }
        __syncthreads();
        if (w == 0) {
            bv = rv[lane]; bi = ri[lane];
            #pragma unroll
            for (int off = 16; off; off >>= 1) {
                float ov = __shfl_down_sync(0xffffffffu, bv, off);
                int   oi = __shfl_down_sync(0xffffffffu, bi, off);
                if (ov > bv || (ov == bv && oi < bi)) { bv = ov; bi = oi; }
            }
            if (lane == 0) s_last = bi;
        }
        __syncthreads();
        last = s_last;
    }
}

// ======================= K_ball: ball query (+ centroid output) =======================
__global__ __launch_bounds__(256) void ballq_kernel(const float* __restrict__ points,
                                                    float* __restrict__ out) {
    extern __shared__ float sm2[];
    float* sx = sm2; float* sy = sm2 + NPTS; float* sz = sm2 + 2 * NPTS;
    const int tid = threadIdx.x, warp = tid >> 5, lane = tid & 31;
    const int b = blockIdx.x >> 7;                 // 128 blocks per batch
    const int m = ((blockIdx.x & 127) << 3) + warp;
    const float* pb = points + b * 3 * NPTS;
    for (int i = tid; i < NPTS; i += 256) { sx[i] = pb[i]; sy[i] = pb[NPTS + i]; sz[i] = pb[2 * NPTS + i]; }
    __syncthreads();
    const int g = b * MCENT + m;
    const int cidx = g_idx[g];
    const float cx = sx[cidx], cy = sy[cidx], cz = sz[cidx];
    if (lane < 3) out[b * 3 * MCENT + m * 3 + lane] = (lane == 0) ? cx : ((lane == 1) ? cy : cz);
    int* selp = g_sel + g * KG;
    int cnt = 0, first = 0;
    const unsigned lt = (1u << lane) - 1u;
    for (int ch = 0; ch < NPTS / 32; ch++) {
        const int i = ch * 32 + lane;
        const float d2 = sq3(cx - sx[i], cy - sy[i], cz - sz[i]);
        const bool pred = (d2 <= 0.04f);           // f32(0.2*0.2 in double)
        const unsigned mask = __ballot_sync(0xffffffffu, pred);
        if (cnt == 0 && mask) first = ch * 32 + __ffs(mask) - 1;
        const int rank = __popc(mask & lt);
        if (pred && cnt + rank < KG) selp[cnt + rank] = i;
        cnt += __popc(mask);
        if (cnt >= KG) break;
    }
    for (int j = cnt + lane; j < KG; j += 32) selp[j] = first;  // pad with smallest hit
}

// ======================= K_mlp: pointwise feature MLP + W1·p =======================
__global__ __launch_bounds__(256) void mlp_points_kernel(
    const float* __restrict__ points, const float* __restrict__ pf,
    const float* __restrict__ pw1,
    const float* __restrict__ fw1, const float* __restrict__ fb1,
    const float* __restrict__ fw2, const float* __restrict__ fb2,
    const float* __restrict__ fw3, const float* __restrict__ fb3) {
    extern __shared__ float sw[];
    float* s_fw1t = sw;                 // [c][o] 64x64
    float* s_fw2t = s_fw1t + 4096;      // [c][o] 64x64
    float* s_fw3t = s_fw2t + 4096;      // [c][o] 64x128
    float* s_pw1t = s_fw3t + 8192;      // [d][o] 3x64
    float* s_fb1  = s_pw1t + 192;
    float* s_fb2  = s_fb1 + 64;
    float* s_fb3  = s_fb2 + 64;
    const int tid = threadIdx.x;
    for (int i = tid; i < 4096; i += 256) {
        const int o = i >> 6, c = i & 63;
        s_fw1t[c * 64 + o] = fw1[i];
        s_fw2t[c * 64 + o] = fw2[i];
    }
    for (int i = tid; i < 8192; i += 256) { const int o = i >> 6, c = i & 63; s_fw3t[c * 128 + o] = fw3[i]; }
    for (int i = tid; i < 192; i += 256)  { const int o = i / 3, d = i % 3;  s_pw1t[d * 64 + o] = pw1[i]; }
    if (tid < 64)  { s_fb1[tid] = fb1[tid]; s_fb2[tid] = fb2[tid]; }
    if (tid < 128) s_fb3[tid] = fb3[tid];
    __syncthreads();
    const int warp = tid >> 5, lane = tid & 31;
    const int pidx = blockIdx.x * 8 + warp;   // 0..32767
    const int b = pidx >> 12, n = pidx & (NPTS - 1);
    // W1·p (no bias / relu)
    const float px = __ldg(&points[b * 3 * NPTS + n]);
    const float py = __ldg(&points[b * 3 * NPTS + NPTS + n]);
    const float pz = __ldg(&points[b * 3 * NPTS + 2 * NPTS + n]);
    float* p1 = ((float*)g_P1v) + (b * NPTS + n) * CIN;
    p1[lane]      = s_pw1t[lane] * px      + s_pw1t[64 + lane] * py      + s_pw1t[128 + lane] * pz;
    p1[32 + lane] = s_pw1t[32 + lane] * px + s_pw1t[96 + lane] * py      + s_pw1t[160 + lane] * pz;
    // feature MLP
    const float* f = pf + b * CIN * NPTS + n;
    float h1a = s_fb1[lane], h1b = s_fb1[32 + lane];
    #pragma unroll 8
    for (int c = 0; c < 64; c++) {
        const float fc = __ldg(&f[c * NPTS]);
        h1a += s_fw1t[c * 64 + lane] * fc;
        h1b += s_fw1t[c * 64 + 32 + lane] * fc;
    }
    h1a = fmaxf(h1a, 0.f); h1b = fmaxf(h1b, 0.f);
    float h2a = s_fb2[lane], h2b = s_fb2[32 + lane];
    #pragma unroll 8
    for (int c = 0; c < 64; c++) {
        const float src = (c < 32) ? h1a : h1b;
        const float v = __shfl_sync(0xffffffffu, src, c & 31);
        h2a += s_fw2t[c * 64 + lane] * v;
        h2b += s_fw2t[c * 64 + 32 + lane] * v;
    }
    h2a = fmaxf(h2a, 0.f); h2b = fmaxf(h2b, 0.f);
    float o0 = s_fb3[lane], o1 = s_fb3[32 + lane], o2 = s_fb3[64 + lane], o3 = s_fb3[96 + lane];
    #pragma unroll 8
    for (int c = 0; c < 64; c++) {
        const float src = (c < 32) ? h2a : h2b;
        const float v = __shfl_sync(0xffffffffu, src, c & 31);
        o0 += s_fw3t[c * 128 + lane] * v;
        o1 += s_fw3t[c * 128 + 32 + lane] * v;
        o2 += s_fw3t[c * 128 + 64 + lane] * v;
        o3 += s_fw3t[c * 128 + 96 + lane] * v;
    }
    float* fo = ((float*)g_Fov) + (b * NPTS + n) * HC;
    fo[lane] = o0; fo[32 + lane] = o1; fo[64 + lane] = o2; fo[96 + lane] = o3;
}

// ======================= K_group: per-group points-MLP L2/L3 + max, feature gather-max =======================
__global__ __launch_bounds__(64) void group_kernel(
    const float* __restrict__ pw2, const float* __restrict__ pb1,
    const float* __restrict__ pb2, const float* __restrict__ pw3,
    const float* __restrict__ pb3, float* __restrict__ out) {
    __shared__ float4 sW2t4[1024];     // W2^T [c][o] 64x64
    __shared__ float4 sQ4[16];         // b1 - W1·c
    __shared__ float  sPb2[64];
    __shared__ int    sSel[64];
    __shared__ float  sMax[256];
    float* sW2t = (float*)sW2t4;
    float* sQ   = (float*)sQ4;
    const int g = blockIdx.x, b = g >> 10, m = g & 1023;
    const int tid = threadIdx.x;       // 64 threads = 64 neighbors
    const int cidx = g_idx[g];
    sQ[tid]   = pb1[tid] - ((const float*)g_P1v)[(b * NPTS + cidx) * CIN + tid];
    sSel[tid] = g_sel[g * KG + tid];
    sPb2[tid] = pb2[tid];
    for (int i = tid; i < 4096; i += 64) { const int o = i >> 6, c = i & 63; sW2t[c * 64 + o] = pw2[i]; }
    __syncthreads();
    const int n = sSel[tid];
    const float4* p1row = (const float4*)(((const float*)g_P1v) + (b * NPTS + n) * CIN);
    float h2[64];
    #pragma unroll
    for (int o = 0; o < 64; o++) h2[o] = sPb2[o];
    #pragma unroll 2
    for (int c4 = 0; c4 < 16; c4++) {
        const float4 p = __ldg(&p1row[c4]);
        const float4 q = sQ4[c4];
        const float a0 = fmaxf(p.x + q.x, 0.f);
        const float a1 = fmaxf(p.y + q.y, 0.f);
        const float a2 = fmaxf(p.z + q.z, 0.f);
        const float a3 = fmaxf(p.w + q.w, 0.f);
        const float4* w0 = (const float4*)(sW2t + (4 * c4 + 0) * 64);
        const float4* w1 = (const float4*)(sW2t + (4 * c4 + 1) * 64);
        const float4* w2 = (const float4*)(sW2t + (4 * c4 + 2) * 64);
        const float4* w3 = (const float4*)(sW2t + (4 * c4 + 3) * 64);
        #pragma unroll
        for (int o4 = 0; o4 < 16; o4++) {
            const float4 wa = w0[o4], wb = w1[o4], wc = w2[o4], wd = w3[o4];
            h2[4 * o4 + 0] += wa.x * a0 + wb.x * a1 + wc.x * a2 + wd.x * a3;
            h2[4 * o4 + 1] += wa.y * a0 + wb.y * a1 + wc.y * a2 + wd.y * a3;
            h2[4 * o4 + 2] += wa.z * a0 + wb.z * a1 + wc.z * a2 + wd.z * a3;
            h2[4 * o4 + 3] += wa.w * a0 + wb.w * a1 + wc.w * a2 + wd.w * a3;
        }
    }
    #pragma unroll
    for (int o = 0; o < 64; o++) h2[o] = fmaxf(h2[o], 0.f);
    const int lane = tid & 31, w = tid >> 5;
    const float4* w3g = (const float4*)pw3;
    for (int o = 0; o < HC; o++) {
        float acc = __ldg(&pb3[o]);
        #pragma unroll
        for (int c4 = 0; c4 < 16; c4++) {
            const float4 wv = __ldg(&w3g[o * 16 + c4]);
            acc += wv.x * h2[4 * c4 + 0] + wv.y * h2[4 * c4 + 1]
                 + wv.z * h2[4 * c4 + 2] + wv.w * h2[4 * c4 + 3];
        }
        #pragma unroll
        for (int off = 16; off; off >>= 1) acc = fmaxf(acc, __shfl_xor_sync(0xffffffffu, acc, off));
        if (lane == 0) sMax[w * HC + o] = acc;
    }
    __syncthreads();
    float* o2 = out + BATCH * 3 * MCENT + b * (2 * HC * MCENT);
    // p_out -> channels [128,256)
    o2[(HC + tid) * MCENT + m]      = fmaxf(sMax[tid],      sMax[HC + tid]);
    o2[(HC + 64 + tid) * MCENT + m] = fmaxf(sMax[64 + tid], sMax[HC + 64 + tid]);
    // f_out -> channels [0,128): pure gather-max of precomputed feature MLP
    #pragma unroll
    for (int j = 0; j < 2; j++) {
        const int o = tid + j * 64;
        const float* fb_ = ((const float*)g_Fov) + b * NPTS * HC + o;
        float v = -3.4e38f;
        #pragma unroll 4
        for (int k = 0; k < KG; k++) v = fmaxf(v, __ldg(&fb_[sSel[k] * HC]));
        o2[o * MCENT + m] = v;
    }
}

// ======================= launch =======================
extern "C" void kernel_launch(void* const* d_in, const int* in_sizes, int n_in,
                              void* d_out, int out_size) {
    const float* points = (const float*)d_in[0];
    const float* pfeat  = (const float*)d_in[1];
    const float* pw1 = (const float*)d_in[2];  const float* pb1 = (const float*)d_in[3];
    const float* pw2 = (const float*)d_in[4];  const float* pb2 = (const float*)d_in[5];
    const float* pw3 = (const float*)d_in[6];  const float* pb3 = (const float*)d_in[7];
    const float* fw1 = (const float*)d_in[8];  const float* fb1 = (const float*)d_in[9];
    const float* fw2 = (const float*)d_in[10]; const float* fb2 = (const float*)d_in[11];
    const float* fw3 = (const float*)d_in[12]; const float* fb3 = (const float*)d_in[13];
    float* out = (float*)d_out;

    cudaFuncSetAttribute(mlp_points_kernel, cudaFuncAttributeMaxDynamicSharedMemorySize, 67328);
    cudaFuncSetAttribute(fps_kernel,        cudaFuncAttributeMaxDynamicSharedMemorySize, 49152);
    cudaFuncSetAttribute(ballq_kernel,      cudaFuncAttributeMaxDynamicSharedMemorySize, 49152);

    mlp_points_kernel<<<BATCH * NPTS / 8, 256, 67328>>>(points, pfeat, pw1,
                                                        fw1, fb1, fw2, fb2, fw3, fb3);
    fps_kernel<<<BATCH, 1024, 49152>>>(points);
    ballq_kernel<<<BATCH * MCENT / 8, 256, 49152>>>(points, out);
    group_kernel<<<BATCH * MCENT, 64>>>(pw2, pb1, pb2, pw3, pb3, out);
}

// round 3
// speedup vs baseline: 1.7460x; 1.7460x over previous
#include <cuda_runtime.h>

#define BATCH 8
#define NPTS  4096
#define MCENT 1024
#define KG    64
#define CIN   64
#define HC    128   // half of C_out

// ---------------- scratch (device globals; no allocation) ----------------
__device__ int    g_idx[BATCH * MCENT];
__device__ int    g_sel[BATCH * MCENT * KG];
__device__ float4 g_P1v[BATCH * NPTS * (CIN / 4)];   // W1·p per point, 64 floats/pt
__device__ float4 g_Fov[BATCH * NPTS * (HC / 4)];    // feature-MLP output, 128 floats/pt

// exact (no-FMA) squared distance, association ((dx^2+dy^2)+dz^2) to match XLA
__device__ __forceinline__ float sq3(float dx, float dy, float dz) {
    return __fadd_rn(__fadd_rn(__fmul_rn(dx, dx), __fmul_rn(dy, dy)), __fmul_rn(dz, dz));
}

// ======================= K_fps: farthest point sampling =======================
// 1 CTA / batch, 1024 threads, 4 points per thread. Exact argmax with
// first-occurrence tie-break via redux_max(value bits) + redux_min(index).
// One barrier per step using parity double-buffered warp results.
__global__ __launch_bounds__(1024) void fps_kernel(const float* __restrict__ points) {
    extern __shared__ float sm[];
    float* sx = sm; float* sy = sm + NPTS; float* sz = sm + 2 * NPTS;
    __shared__ unsigned svb[2][32];
    __shared__ unsigned sib[2][32];
    const int b = blockIdx.x, tid = threadIdx.x;
    const int lane = tid & 31, w = tid >> 5;
    const float* pb = points + b * 3 * NPTS;
    for (int i = tid; i < NPTS; i += 1024) { sx[i] = pb[i]; sy[i] = pb[NPTS + i]; sz[i] = pb[2 * NPTS + i]; }
    __syncthreads();
    const int i0 = tid * 4;
    const float x0 = sx[i0 + 0], y0 = sy[i0 + 0], z0 = sz[i0 + 0];
    const float x1 = sx[i0 + 1], y1 = sy[i0 + 1], z1 = sz[i0 + 1];
    const float x2 = sx[i0 + 2], y2 = sy[i0 + 2], z2 = sz[i0 + 2];
    const float x3 = sx[i0 + 3], y3 = sy[i0 + 3], z3 = sz[i0 + 3];
    float m0 = 1e30f, m1 = 1e30f, m2 = 1e30f, m3 = 1e30f;
    int last = 0;
    for (int s = 0; s < MCENT; s++) {
        if (tid == 0) g_idx[b * MCENT + s] = last;
        const float lx = sx[last], ly = sy[last], lz = sz[last];
        m0 = fminf(m0, sq3(x0 - lx, y0 - ly, z0 - lz));
        m1 = fminf(m1, sq3(x1 - lx, y1 - ly, z1 - lz));
        m2 = fminf(m2, sq3(x2 - lx, y2 - ly, z2 - lz));
        m3 = fminf(m3, sq3(x3 - lx, y3 - ly, z3 - lz));
        float bv = m0; int bi = i0;                 // strictly-greater keeps first max
        if (m1 > bv) { bv = m1; bi = i0 + 1; }
        if (m2 > bv) { bv = m2; bi = i0 + 2; }
        if (m3 > bv) { bv = m3; bi = i0 + 3; }
        // warp stage: exact argmax (value max, then min index among equals)
        const unsigned vb = __float_as_uint(bv);    // distances >= 0: bit order == float order
        const unsigned wmax = __reduce_max_sync(0xffffffffu, vb);
        const unsigned cand = (vb == wmax) ? (unsigned)bi : 0xffffffffu;
        const unsigned imin = __reduce_min_sync(0xffffffffu, cand);
        const int par = s & 1;
        if (lane == 0) { svb[par][w] = wmax; sib[par][w] = imin; }
        __syncthreads();
        // every warp reduces the 32 warp results identically (no 2nd barrier;
        // parity buffer makes next iteration's writes race-free)
        const unsigned v2 = svb[par][lane];
        const unsigned i2 = sib[par][lane];
        const unsigned gm = __reduce_max_sync(0xffffffffu, v2);
        const unsigned c2 = (v2 == gm) ? i2 : 0xffffffffu;
        last = (int)__reduce_min_sync(0xffffffffu, c2);
    }
}

// ======================= K_ball: ball query (+ centroid output) =======================
__global__ __launch_bounds__(256) void ballq_kernel(const float* __restrict__ points,
                                                    float* __restrict__ out) {
    extern __shared__ float sm2[];
    float* sx = sm2; float* sy = sm2 + NPTS; float* sz = sm2 + 2 * NPTS;
    const int tid = threadIdx.x, warp = tid >> 5, lane = tid & 31;
    const int b = blockIdx.x >> 7;                 // 128 blocks per batch
    const int m = ((blockIdx.x & 127) << 3) + warp;
    const float* pb = points + b * 3 * NPTS;
    for (int i = tid; i < NPTS; i += 256) { sx[i] = pb[i]; sy[i] = pb[NPTS + i]; sz[i] = pb[2 * NPTS + i]; }
    __syncthreads();
    const int g = b * MCENT + m;
    const int cidx = g_idx[g];
    const float cx = sx[cidx], cy = sy[cidx], cz = sz[cidx];
    if (lane < 3) out[b * 3 * MCENT + m * 3 + lane] = (lane == 0) ? cx : ((lane == 1) ? cy : cz);
    int* selp = g_sel + g * KG;
    int cnt = 0, first = 0;
    const unsigned lt = (1u << lane) - 1u;
    for (int ch = 0; ch < NPTS / 32; ch++) {
        const int i = ch * 32 + lane;
        const float d2 = sq3(cx - sx[i], cy - sy[i], cz - sz[i]);
        const bool pred = (d2 <= 0.04f);           // f32(0.2*0.2 in double)
        const unsigned mask = __ballot_sync(0xffffffffu, pred);
        if (cnt == 0 && mask) first = ch * 32 + __ffs(mask) - 1;
        const int rank = __popc(mask & lt);
        if (pred && cnt + rank < KG) selp[cnt + rank] = i;
        cnt += __popc(mask);
        if (cnt >= KG) break;
    }
    for (int j = cnt + lane; j < KG; j += 32) selp[j] = first;  // pad with smallest hit
}

// ======================= K_mlp: pointwise feature MLP + W1·p =======================
__global__ __launch_bounds__(256) void mlp_points_kernel(
    const float* __restrict__ points, const float* __restrict__ pf,
    const float* __restrict__ pw1,
    const float* __restrict__ fw1, const float* __restrict__ fb1,
    const float* __restrict__ fw2, const float* __restrict__ fb2,
    const float* __restrict__ fw3, const float* __restrict__ fb3) {
    extern __shared__ float sw[];
    float* s_fw1t = sw;                 // [c][o] 64x64
    float* s_fw2t = s_fw1t + 4096;      // [c][o] 64x64
    float* s_fw3t = s_fw2t + 4096;      // [c][o] 64x128
    float* s_pw1t = s_fw3t + 8192;      // [d][o] 3x64
    float* s_fb1  = s_pw1t + 192;
    float* s_fb2  = s_fb1 + 64;
    float* s_fb3  = s_fb2 + 64;
    const int tid = threadIdx.x;
    for (int i = tid; i < 4096; i += 256) {
        const int o = i >> 6, c = i & 63;
        s_fw1t[c * 64 + o] = fw1[i];
        s_fw2t[c * 64 + o] = fw2[i];
    }
    for (int i = tid; i < 8192; i += 256) { const int o = i >> 6, c = i & 63; s_fw3t[c * 128 + o] = fw3[i]; }
    for (int i = tid; i < 192; i += 256)  { const int o = i / 3, d = i % 3;  s_pw1t[d * 64 + o] = pw1[i]; }
    if (tid < 64)  { s_fb1[tid] = fb1[tid]; s_fb2[tid] = fb2[tid]; }
    if (tid < 128) s_fb3[tid] = fb3[tid];
    __syncthreads();
    const int warp = tid >> 5, lane = tid & 31;
    const int pidx = blockIdx.x * 8 + warp;   // 0..32767
    const int b = pidx >> 12, n = pidx & (NPTS - 1);
    // W1·p (no bias / relu)
    const float px = __ldg(&points[b * 3 * NPTS + n]);
    const float py = __ldg(&points[b * 3 * NPTS + NPTS + n]);
    const float pz = __ldg(&points[b * 3 * NPTS + 2 * NPTS + n]);
    float* p1 = ((float*)g_P1v) + (b * NPTS + n) * CIN;
    p1[lane]      = s_pw1t[lane] * px      + s_pw1t[64 + lane] * py      + s_pw1t[128 + lane] * pz;
    p1[32 + lane] = s_pw1t[32 + lane] * px + s_pw1t[96 + lane] * py      + s_pw1t[160 + lane] * pz;
    // feature MLP
    const float* f = pf + b * CIN * NPTS + n;
    float h1a = s_fb1[lane], h1b = s_fb1[32 + lane];
    #pragma unroll 8
    for (int c = 0; c < 64; c++) {
        const float fc = __ldg(&f[c * NPTS]);
        h1a += s_fw1t[c * 64 + lane] * fc;
        h1b += s_fw1t[c * 64 + 32 + lane] * fc;
    }
    h1a = fmaxf(h1a, 0.f); h1b = fmaxf(h1b, 0.f);
    float h2a = s_fb2[lane], h2b = s_fb2[32 + lane];
    #pragma unroll 8
    for (int c = 0; c < 64; c++) {
        const float src = (c < 32) ? h1a : h1b;
        const float v = __shfl_sync(0xffffffffu, src, c & 31);
        h2a += s_fw2t[c * 64 + lane] * v;
        h2b += s_fw2t[c * 64 + 32 + lane] * v;
    }
    h2a = fmaxf(h2a, 0.f); h2b = fmaxf(h2b, 0.f);
    float o0 = s_fb3[lane], o1 = s_fb3[32 + lane], o2 = s_fb3[64 + lane], o3 = s_fb3[96 + lane];
    #pragma unroll 8
    for (int c = 0; c < 64; c++) {
        const float src = (c < 32) ? h2a : h2b;
        const float v = __shfl_sync(0xffffffffu, src, c & 31);
        o0 += s_fw3t[c * 128 + lane] * v;
        o1 += s_fw3t[c * 128 + 32 + lane] * v;
        o2 += s_fw3t[c * 128 + 64 + lane] * v;
        o3 += s_fw3t[c * 128 + 96 + lane] * v;
    }
    float* fo = ((float*)g_Fov) + (b * NPTS + n) * HC;
    fo[lane] = o0; fo[32 + lane] = o1; fo[64 + lane] = o2; fo[96 + lane] = o3;
}

// ======================= K_group =======================
// 128 threads / group. Phase A: thread (k, half) computes 32 h2 channels,
// stores h2 transposed [o][k]. Phase B: thread = output channel o (W3 row in
// registers), k-blocked x4 via broadcast LDS.128; no reductions.
__global__ __launch_bounds__(128) void group_kernel(
    const float* __restrict__ pw2, const float* __restrict__ pb1,
    const float* __restrict__ pb2, const float* __restrict__ pw3,
    const float* __restrict__ pb3, float* __restrict__ out) {
    __shared__ float4 sW2t4[1024];     // W2^T [c][o] 64x64
    __shared__ float4 sH2t4[1024];     // h2^T [o][k] 64x64
    __shared__ float4 sQ4[16];         // b1 - W1·c
    __shared__ int    sSel[64];
    float* sW2t = (float*)sW2t4;
    float* sH2t = (float*)sH2t4;
    float* sQ   = (float*)sQ4;
    const int g = blockIdx.x, b = g >> 10, m = g & 1023;
    const int tid = threadIdx.x;
    const int k = tid & 63, half = tid >> 6;

    if (tid < 64) {
        const int cidx = g_idx[g];
        sQ[tid]   = __ldg(&pb1[tid]) - ((const float*)g_P1v)[(b * NPTS + cidx) * CIN + tid];
        sSel[tid] = g_sel[g * KG + tid];
    }
    for (int i = tid; i < 4096; i += 128) { const int o = i >> 6, c = i & 63; sW2t[c * 64 + o] = pw2[i]; }
    __syncthreads();

    // ---- Phase A: layer 2 (h2 = relu(W2·relu(p1[n] + q))) ----
    const int n = sSel[k];
    const float4* p1row = (const float4*)(((const float*)g_P1v) + (b * NPTS + n) * CIN);
    const int obase = half * 32;
    float acc[32];
    #pragma unroll
    for (int j = 0; j < 32; j++) acc[j] = __ldg(&pb2[obase + j]);
    for (int c4 = 0; c4 < 16; c4++) {
        const float4 p = __ldg(&p1row[c4]);
        const float4 q = sQ4[c4];
        const float a0 = fmaxf(p.x + q.x, 0.f);
        const float a1 = fmaxf(p.y + q.y, 0.f);
        const float a2 = fmaxf(p.z + q.z, 0.f);
        const float a3 = fmaxf(p.w + q.w, 0.f);
        const float4* w0 = (const float4*)(sW2t + (4 * c4 + 0) * 64 + obase);
        const float4* w1 = (const float4*)(sW2t + (4 * c4 + 1) * 64 + obase);
        const float4* w2 = (const float4*)(sW2t + (4 * c4 + 2) * 64 + obase);
        const float4* w3 = (const float4*)(sW2t + (4 * c4 + 3) * 64 + obase);
        #pragma unroll
        for (int j4 = 0; j4 < 8; j4++) {
            const float4 wa = w0[j4], wb = w1[j4], wc = w2[j4], wd = w3[j4];
            acc[4 * j4 + 0] += wa.x * a0 + wb.x * a1 + wc.x * a2 + wd.x * a3;
            acc[4 * j4 + 1] += wa.y * a0 + wb.y * a1 + wc.y * a2 + wd.y * a3;
            acc[4 * j4 + 2] += wa.z * a0 + wb.z * a1 + wc.z * a2 + wd.z * a3;
            acc[4 * j4 + 3] += wa.w * a0 + wb.w * a1 + wc.w * a2 + wd.w * a3;
        }
    }
    #pragma unroll
    for (int j = 0; j < 32; j++) sH2t[(obase + j) * 64 + k] = fmaxf(acc[j], 0.f);
    __syncthreads();

    // ---- Phase B: layer 3 + max over neighbors; thread = output channel ----
    float4 wreg[16];
    const float4* w3r = (const float4*)(pw3 + tid * 64);
    #pragma unroll
    for (int i = 0; i < 16; i++) wreg[i] = __ldg(&w3r[i]);
    const float bo = __ldg(&pb3[tid]);
    float vmax = -3.4e38f;
    for (int kb = 0; kb < 16; kb++) {
        float a0 = bo, a1 = bo, a2 = bo, a3 = bo;
        #pragma unroll
        for (int c = 0; c < 64; c++) {
            const float4 h = sH2t4[c * 16 + kb];   // neighbors 4kb..4kb+3, channel c (broadcast)
            const float  w = ((const float*)wreg)[c];
            a0 += w * h.x; a1 += w * h.y; a2 += w * h.z; a3 += w * h.w;
        }
        vmax = fmaxf(vmax, fmaxf(fmaxf(a0, a1), fmaxf(a2, a3)));
    }
    float* o2 = out + BATCH * 3 * MCENT + b * (2 * HC * MCENT);
    o2[(HC + tid) * MCENT + m] = vmax;             // p_out -> channels [128,256)

    // f_out -> channels [0,128): gather-max of precomputed feature MLP
    const float* fb_ = ((const float*)g_Fov) + b * NPTS * HC + tid;
    float v = -3.4e38f;
    #pragma unroll 8
    for (int kk = 0; kk < KG; kk++) v = fmaxf(v, __ldg(&fb_[sSel[kk] * HC]));
    o2[tid * MCENT + m] = v;
}

// ======================= launch =======================
extern "C" void kernel_launch(void* const* d_in, const int* in_sizes, int n_in,
                              void* d_out, int out_size) {
    const float* points = (const float*)d_in[0];
    const float* pfeat  = (const float*)d_in[1];
    const float* pw1 = (const float*)d_in[2];  const float* pb1 = (const float*)d_in[3];
    const float* pw2 = (const float*)d_in[4];  const float* pb2 = (const float*)d_in[5];
    const float* pw3 = (const float*)d_in[6];  const float* pb3 = (const float*)d_in[7];
    const float* fw1 = (const float*)d_in[8];  const float* fb1 = (const float*)d_in[9];
    const float* fw2 = (const float*)d_in[10]; const float* fb2 = (const float*)d_in[11];
    const float* fw3 = (const float*)d_in[12]; const float* fb3 = (const float*)d_in[13];
    float* out = (float*)d_out;

    cudaFuncSetAttribute(mlp_points_kernel, cudaFuncAttributeMaxDynamicSharedMemorySize, 67328);
    cudaFuncSetAttribute(fps_kernel,        cudaFuncAttributeMaxDynamicSharedMemorySize, 49152);
    cudaFuncSetAttribute(ballq_kernel,      cudaFuncAttributeMaxDynamicSharedMemorySize, 49152);

    mlp_points_kernel<<<BATCH * NPTS / 8, 256, 67328>>>(points, pfeat, pw1,
                                                        fw1, fb1, fw2, fb2, fw3, fb3);
    fps_kernel<<<BATCH, 1024, 49152>>>(points);
    ballq_kernel<<<BATCH * MCENT / 8, 256, 49152>>>(points, out);
    group_kernel<<<BATCH * MCENT, 128>>>(pw2, pb1, pb2, pw3, pb3, out);
}

// round 6
// speedup vs baseline: 2.4009x; 1.3751x over previous
#include <cuda_runtime.h>

#define BATCH 8
#define NPTS  4096
#define MCENT 1024
#define KG    64
#define CIN   64
#define HC    128   // half of C_out

// ---------------- scratch (device globals; no allocation) ----------------
__device__ int    g_idx[BATCH * MCENT];
__device__ int    g_sel[BATCH * MCENT * KG];
__device__ float4 g_P1v[BATCH * NPTS * (CIN / 4)];   // W1·p per point, 64 floats/pt
__device__ float4 g_Fov[BATCH * NPTS * (HC / 4)];    // feature-MLP output, 128 floats/pt
__device__ float  g_W3t[CIN * HC];                   // W3^T [c][o] 64x128

// exact (no-FMA) squared distance, association ((dx^2+dy^2)+dz^2) to match XLA
__device__ __forceinline__ float sq3(float dx, float dy, float dz) {
    return __fadd_rn(__fadd_rn(__fmul_rn(dx, dx), __fmul_rn(dy, dy)), __fmul_rn(dz, dz));
}

// ======================= prep kernel: fps (blocks 0..7) | W3 transpose (8) | mlp (9..) ==========
__global__ __launch_bounds__(1024) void prep_kernel(
    const float* __restrict__ points, const float* __restrict__ pf,
    const float* __restrict__ pw1, const float* __restrict__ pw3,
    const float* __restrict__ fw1, const float* __restrict__ fb1,
    const float* __restrict__ fw2, const float* __restrict__ fb2,
    const float* __restrict__ fw3, const float* __restrict__ fb3) {
    extern __shared__ float sm[];
    const int tid = threadIdx.x;

    if (blockIdx.x < 8) {
        // ---------------- FPS: 1 CTA / batch ----------------
        float* sx = sm; float* sy = sm + NPTS; float* sz = sm + 2 * NPTS;
        __shared__ unsigned svb[2][32];
        __shared__ unsigned sib[2][32];
        const int b = blockIdx.x;
        const int lane = tid & 31, w = tid >> 5;
        const float* pb = points + b * 3 * NPTS;
        for (int i = tid; i < NPTS; i += 1024) { sx[i] = pb[i]; sy[i] = pb[NPTS + i]; sz[i] = pb[2 * NPTS + i]; }
        __syncthreads();
        const int i0 = tid * 4;
        const float x0 = sx[i0 + 0], y0 = sy[i0 + 0], z0 = sz[i0 + 0];
        const float x1 = sx[i0 + 1], y1 = sy[i0 + 1], z1 = sz[i0 + 1];
        const float x2 = sx[i0 + 2], y2 = sy[i0 + 2], z2 = sz[i0 + 2];
        const float x3 = sx[i0 + 3], y3 = sy[i0 + 3], z3 = sz[i0 + 3];
        float m0 = 1e30f, m1 = 1e30f, m2 = 1e30f, m3 = 1e30f;
        int last = 0;
        for (int s = 0; s < MCENT; s++) {
            if (tid == 0) g_idx[b * MCENT + s] = last;
            const float lx = sx[last], ly = sy[last], lz = sz[last];
            m0 = fminf(m0, sq3(x0 - lx, y0 - ly, z0 - lz));
            m1 = fminf(m1, sq3(x1 - lx, y1 - ly, z1 - lz));
            m2 = fminf(m2, sq3(x2 - lx, y2 - ly, z2 - lz));
            m3 = fminf(m3, sq3(x3 - lx, y3 - ly, z3 - lz));
            float bv = m0; int bi = i0;                 // strictly-greater keeps first max
            if (m1 > bv) { bv = m1; bi = i0 + 1; }
            if (m2 > bv) { bv = m2; bi = i0 + 2; }
            if (m3 > bv) { bv = m3; bi = i0 + 3; }
            const unsigned vb = __float_as_uint(bv);    // nonneg floats: bit order == value order
            const unsigned wmax = __reduce_max_sync(0xffffffffu, vb);
            const unsigned cand = (vb == wmax) ? (unsigned)bi : 0xffffffffu;
            const unsigned imin = __reduce_min_sync(0xffffffffu, cand);
            const int par = s & 1;
            if (lane == 0) { svb[par][w] = wmax; sib[par][w] = imin; }
            __syncthreads();
            const unsigned v2 = svb[par][lane];
            const unsigned i2 = sib[par][lane];
            const unsigned gm = __reduce_max_sync(0xffffffffu, v2);
            const unsigned c2 = (v2 == gm) ? i2 : 0xffffffffu;
            last = (int)__reduce_min_sync(0xffffffffu, c2);
        }
        return;
    }
    if (blockIdx.x == 8) {
        // ---------------- W3 transpose ----------------
        for (int i = tid; i < CIN * HC; i += 1024) {
            const int o = i >> 6, c = i & 63;
            g_W3t[c * HC + o] = pw3[i];
        }
        return;
    }

    // ---------------- pointwise MLP: 32 points / block ----------------
    float* s_fw1t = sm;                 // [c][o] 64x64
    float* s_fw2t = s_fw1t + 4096;      // [c][o] 64x64
    float* s_fw3t = s_fw2t + 4096;      // [c][o] 64x128
    float* s_pw1t = s_fw3t + 8192;      // [d][o] 3x64
    float* s_fb1  = s_pw1t + 192;
    float* s_fb2  = s_fb1 + 64;
    float* s_fb3  = s_fb2 + 64;
    for (int i = tid; i < 4096; i += 1024) {
        const int o = i >> 6, c = i & 63;
        s_fw1t[c * 64 + o] = fw1[i];
        s_fw2t[c * 64 + o] = fw2[i];
    }
    for (int i = tid; i < 8192; i += 1024) { const int o = i >> 6, c = i & 63; s_fw3t[c * 128 + o] = fw3[i]; }
    for (int i = tid; i < 192; i += 1024)  { const int o = i / 3, d = i % 3;  s_pw1t[d * 64 + o] = pw1[i]; }
    if (tid < 64)  { s_fb1[tid] = fb1[tid]; s_fb2[tid] = fb2[tid]; }
    if (tid < 128) s_fb3[tid] = fb3[tid];
    __syncthreads();
    const int warp = tid >> 5, lane = tid & 31;
    const int pidx = (blockIdx.x - 9) * 32 + warp;   // 0..32767
    const int b = pidx >> 12, n = pidx & (NPTS - 1);
    // W1·p (no bias / relu)
    const float px = __ldg(&points[b * 3 * NPTS + n]);
    const float py = __ldg(&points[b * 3 * NPTS + NPTS + n]);
    const float pz = __ldg(&points[b * 3 * NPTS + 2 * NPTS + n]);
    float* p1 = ((float*)g_P1v) + (b * NPTS + n) * CIN;
    p1[lane]      = s_pw1t[lane] * px      + s_pw1t[64 + lane] * py      + s_pw1t[128 + lane] * pz;
    p1[32 + lane] = s_pw1t[32 + lane] * px + s_pw1t[96 + lane] * py      + s_pw1t[160 + lane] * pz;
    // feature MLP
    const float* f = pf + b * CIN * NPTS + n;
    float h1a = s_fb1[lane], h1b = s_fb1[32 + lane];
    #pragma unroll 8
    for (int c = 0; c < 64; c++) {
        const float fc = __ldg(&f[c * NPTS]);
        h1a += s_fw1t[c * 64 + lane] * fc;
        h1b += s_fw1t[c * 64 + 32 + lane] * fc;
    }
    h1a = fmaxf(h1a, 0.f); h1b = fmaxf(h1b, 0.f);
    float h2a = s_fb2[lane], h2b = s_fb2[32 + lane];
    #pragma unroll 8
    for (int c = 0; c < 64; c++) {
        const float src = (c < 32) ? h1a : h1b;
        const float v = __shfl_sync(0xffffffffu, src, c & 31);
        h2a += s_fw2t[c * 64 + lane] * v;
        h2b += s_fw2t[c * 64 + 32 + lane] * v;
    }
    h2a = fmaxf(h2a, 0.f); h2b = fmaxf(h2b, 0.f);
    float o0 = s_fb3[lane], o1 = s_fb3[32 + lane], o2 = s_fb3[64 + lane], o3 = s_fb3[96 + lane];
    #pragma unroll 8
    for (int c = 0; c < 64; c++) {
        const float src = (c < 32) ? h2a : h2b;
        const float v = __shfl_sync(0xffffffffu, src, c & 31);
        o0 += s_fw3t[c * 128 + lane] * v;
        o1 += s_fw3t[c * 128 + 32 + lane] * v;
        o2 += s_fw3t[c * 128 + 64 + lane] * v;
        o3 += s_fw3t[c * 128 + 96 + lane] * v;
    }
    float* fo = ((float*)g_Fov) + (b * NPTS + n) * HC;
    fo[lane] = o0; fo[32 + lane] = o1; fo[64 + lane] = o2; fo[96 + lane] = o3;
}

// ======================= K_ball: ball query (+ centroid output) =======================
__global__ __launch_bounds__(256) void ballq_kernel(const float* __restrict__ points,
                                                    float* __restrict__ out) {
    extern __shared__ float sm2[];
    float* sx = sm2; float* sy = sm2 + NPTS; float* sz = sm2 + 2 * NPTS;
    const int tid = threadIdx.x, warp = tid >> 5, lane = tid & 31;
    const int b = blockIdx.x >> 7;                 // 128 blocks per batch
    const int m = ((blockIdx.x & 127) << 3) + warp;
    const float* pb = points + b * 3 * NPTS;
    for (int i = tid; i < NPTS; i += 256) { sx[i] = pb[i]; sy[i] = pb[NPTS + i]; sz[i] = pb[2 * NPTS + i]; }
    __syncthreads();
    const int g = b * MCENT + m;
    const int cidx = g_idx[g];
    const float cx = sx[cidx], cy = sy[cidx], cz = sz[cidx];
    if (lane < 3) out[b * 3 * MCENT + m * 3 + lane] = (lane == 0) ? cx : ((lane == 1) ? cy : cz);
    int* selp = g_sel + g * KG;
    int cnt = 0, first = 0;
    const unsigned lt = (1u << lane) - 1u;
    for (int ch = 0; ch < NPTS / 32; ch++) {
        const int i = ch * 32 + lane;
        const float d2 = sq3(cx - sx[i], cy - sy[i], cz - sz[i]);
        const bool pred = (d2 <= 0.04f);           // f32(0.2*0.2 in double)
        const unsigned mask = __ballot_sync(0xffffffffu, pred);
        if (cnt == 0 && mask) first = ch * 32 + __ffs(mask) - 1;
        const int rank = __popc(mask & lt);
        if (pred && cnt + rank < KG) selp[cnt + rank] = i;
        cnt += __popc(mask);
        if (cnt >= KG) break;
    }
    for (int j = cnt + lane; j < KG; j += 32) selp[j] = first;  // pad with smallest hit
}

// ======================= K_group =======================
// 256 threads / group.
// Phase A: thread (k, q) computes 16 h2 channels for neighbor k, stores h2^T [c][k].
// Phase B: register tile 8 outputs x 4 neighbors; W3^T streamed from global (L1),
//          h2^T from smem; max over k via 4 local + shfl(width 16).
__global__ __launch_bounds__(256, 3) void group_kernel(
    const float* __restrict__ pw2, const float* __restrict__ pb1,
    const float* __restrict__ pb2, const float* __restrict__ pb3,
    float* __restrict__ out) {
    __shared__ float sW2t[4096];       // W2^T [c][o] 64x64 (reused as reduction buf later)
    __shared__ float sH2t[4096];       // h2^T [c][k] 64x64
    __shared__ float4 sQ4[16];         // b1 - W1·centroid
    __shared__ int    sSel[64];
    const int g = blockIdx.x, b = g >> 10, m = g & 1023;
    const int tid = threadIdx.x;

    if (tid < 64) {
        const int cidx = g_idx[g];
        ((float*)sQ4)[tid] = __ldg(&pb1[tid]) - ((const float*)g_P1v)[(b * NPTS + cidx) * CIN + tid];
        sSel[tid] = g_sel[g * KG + tid];
    }
    for (int i = tid; i < 4096; i += 256) { const int o = i >> 6, c = i & 63; sW2t[c * 64 + o] = pw2[i]; }
    __syncthreads();

    // ---- Phase A: h2 = relu(W2·relu(p1[n] + q) + b2) ----
    {
        const int k = tid & 63, q = tid >> 6;      // warp-uniform q
        const int obase = q * 16;
        const int n = sSel[k];
        const float4* p1row = (const float4*)(((const float*)g_P1v) + (b * NPTS + n) * CIN);
        float acc[16];
        #pragma unroll
        for (int j = 0; j < 16; j++) acc[j] = __ldg(&pb2[obase + j]);
        #pragma unroll 4
        for (int c4 = 0; c4 < 16; c4++) {
            const float4 p = __ldg(&p1row[c4]);
            const float4 qv = sQ4[c4];
            float a[4];
            a[0] = fmaxf(p.x + qv.x, 0.f);
            a[1] = fmaxf(p.y + qv.y, 0.f);
            a[2] = fmaxf(p.z + qv.z, 0.f);
            a[3] = fmaxf(p.w + qv.w, 0.f);
            #pragma unroll
            for (int cc = 0; cc < 4; cc++) {
                const float4* wrow = (const float4*)(sW2t + (4 * c4 + cc) * 64 + obase);
                #pragma unroll
                for (int j4 = 0; j4 < 4; j4++) {
                    const float4 wv = wrow[j4];
                    acc[4 * j4 + 0] += wv.x * a[cc];
                    acc[4 * j4 + 1] += wv.y * a[cc];
                    acc[4 * j4 + 2] += wv.z * a[cc];
                    acc[4 * j4 + 3] += wv.w * a[cc];
                }
            }
        }
        #pragma unroll
        for (int j = 0; j < 16; j++) sH2t[(obase + j) * 64 + k] = fmaxf(acc[j], 0.f);
    }
    __syncthreads();

    // ---- Phase B: out[o] = b3[o] + max_k sum_c W3[o,c]*h2[c,k] ----
    {
        const int og = tid >> 4, kg = tid & 15;    // 8-output x 4-neighbor tile
        float ak0[8], ak1[8], ak2[8], ak3[8];
        #pragma unroll
        for (int j = 0; j < 8; j++) { ak0[j] = 0.f; ak1[j] = 0.f; ak2[j] = 0.f; ak3[j] = 0.f; }
        const float4* w3ta = (const float4*)(g_W3t + og * 8);
        const float4* hP   = (const float4*)(sH2t + kg * 4);
        #pragma unroll 8
        for (int c = 0; c < 64; c++) {
            const float4 h  = hP[c * 16];                    // h2t[c][4kg..]
            const float4 wa = __ldg(&w3ta[c * 32]);          // W3t[c][8og..]
            const float4 wb = __ldg(&w3ta[c * 32 + 1]);
            const float w[8] = {wa.x, wa.y, wa.z, wa.w, wb.x, wb.y, wb.z, wb.w};
            #pragma unroll
            for (int j = 0; j < 8; j++) {
                ak0[j] += w[j] * h.x;
                ak1[j] += w[j] * h.y;
                ak2[j] += w[j] * h.z;
                ak3[j] += w[j] * h.w;
            }
        }
        float* o2 = out + BATCH * 3 * MCENT + b * (2 * HC * MCENT);
        #pragma unroll
        for (int j = 0; j < 8; j++) {
            float v = fmaxf(fmaxf(ak0[j], ak1[j]), fmaxf(ak2[j], ak3[j]));
            v = fmaxf(v, __shfl_down_sync(0xffffffffu, v, 8, 16));
            v = fmaxf(v, __shfl_down_sync(0xffffffffu, v, 4, 16));
            v = fmaxf(v, __shfl_down_sync(0xffffffffu, v, 2, 16));
            v = fmaxf(v, __shfl_down_sync(0xffffffffu, v, 1, 16));
            if (kg == 0) {
                const int o = og * 8 + j;
                o2[(HC + o) * MCENT + m] = v + __ldg(&pb3[o]);   // p_out -> channels [128,256)
            }
        }
    }

    // ---- f_out (channels [0,128)): gather-max of precomputed feature MLP ----
    {
        const int o = tid & 127, kh = tid >> 7;
        const float* fb_ = ((const float*)g_Fov) + b * NPTS * HC + o;
        float v = -3.4e38f;
        #pragma unroll 8
        for (int kk = 0; kk < 32; kk++) v = fmaxf(v, __ldg(&fb_[sSel[kh * 32 + kk] * HC]));
        if (kh) sW2t[o] = v;                       // sW2t reused as reduction buffer
        __syncthreads();
        if (!kh) {
            float* o2 = out + BATCH * 3 * MCENT + b * (2 * HC * MCENT);
            o2[o * MCENT + m] = fmaxf(v, sW2t[o]);
        }
    }
}

// ======================= launch =======================
extern "C" void kernel_launch(void* const* d_in, const int* in_sizes, int n_in,
                              void* d_out, int out_size) {
    const float* points = (const float*)d_in[0];
    const float* pfeat  = (const float*)d_in[1];
    const float* pw1 = (const float*)d_in[2];  const float* pb1 = (const float*)d_in[3];
    const float* pw2 = (const float*)d_in[4];  const float* pb2 = (const float*)d_in[5];
    const float* pw3 = (const float*)d_in[6];  const float* pb3 = (const float*)d_in[7];
    const float* fw1 = (const float*)d_in[8];  const float* fb1 = (const float*)d_in[9];
    const float* fw2 = (const float*)d_in[10]; const float* fb2 = (const float*)d_in[11];
    const float* fw3 = (const float*)d_in[12]; const float* fb3 = (const float*)d_in[13];
    float* out = (float*)d_out;

    cudaFuncSetAttribute(prep_kernel,  cudaFuncAttributeMaxDynamicSharedMemorySize, 67328);
    cudaFuncSetAttribute(ballq_kernel, cudaFuncAttributeMaxDynamicSharedMemorySize, 49152);

    prep_kernel<<<8 + 1 + 1024, 1024, 67328>>>(points, pfeat, pw1, pw3,
                                               fw1, fb1, fw2, fb2, fw3, fb3);
    ballq_kernel<<<BATCH * MCENT / 8, 256, 49152>>>(points, out);
    group_kernel<<<BATCH * MCENT, 256>>>(pw2, pb1, pb2, pb3, out);
}